// round 15
// baseline (speedup 1.0000x reference)
#include <cuda_runtime.h>
#include <cuda_bf16.h>
#include <cuda_fp16.h>
#include <cstdint>

#define NN 8192        // nodes
#define NW 256         // mask words per row (8192/32)
#define DIM 128
#define LDW 136        // padded bf16 row stride (272 B) -> conflict-free ldmatrix

// exp(-ALPHA*k), ALPHA=2
#define F1 0.13533528323661270f
#define F2 0.018315638888734179f
#define F3 0.0024787521766663585f

// ---------------- scratch (static device globals; no allocation) ----------------
__device__ unsigned g_adj[NN * NW];   // 8 MB adjacency bitmask (zeroed by k_zero for next replay)
__device__ unsigned g_P2[NN * NW];    // 8 MB bool(adj^2)
__device__ unsigned g_P3[NN * NW];    // 8 MB bool(adj^3)
__device__ float    g_ang[NN];
__device__ float    g_s1[NN];
__device__ float    g_enh1[NN];
__device__ float    g_s2[NN];
__device__ float    g_enh2[NN];
__device__ short    g_nl[NN * 128];   // 2 MB neighbor lists (capped 128)
__device__ int      g_ncap[NN];
__device__ int      g_ndup;
__device__ int      g_dupr[4096];
__device__ int      g_dupc[4096];
__device__ __align__(16) __nv_bfloat16 g_Whi[3][DIM * LDW];  // pre-split W, [n][k] padded
__device__ __align__(16) __nv_bfloat16 g_Wlo[3][DIM * LDW];

// ================= PTX helpers (family-agnostic ISA only) =================
__device__ __forceinline__ uint32_t smem_u32(const void* p) {
    uint32_t a;
    asm("{ .reg .u64 t; cvta.to.shared.u64 t, %1; cvt.u32.u64 %0, t; }" : "=r"(a) : "l"(p));
    return a;
}
__device__ __forceinline__ void ldm_x4(uint32_t* r, uint32_t addr) {
    asm volatile("ldmatrix.sync.aligned.m8n8.x4.shared.b16 {%0,%1,%2,%3}, [%4];"
                 : "=r"(r[0]), "=r"(r[1]), "=r"(r[2]), "=r"(r[3]) : "r"(addr));
}
__device__ __forceinline__ void mma_bf16(float* c, const uint32_t* a, uint32_t b0, uint32_t b1) {
    asm volatile(
        "mma.sync.aligned.m16n8k16.row.col.f32.bf16.bf16.f32 "
        "{%0,%1,%2,%3}, {%4,%5,%6,%7}, {%8,%9}, {%0,%1,%2,%3};"
        : "+f"(c[0]), "+f"(c[1]), "+f"(c[2]), "+f"(c[3])
        : "r"(a[0]), "r"(a[1]), "r"(a[2]), "r"(a[3]), "r"(b0), "r"(b1));
}

// ---------------- prep: split W into bf16 hi/lo [n][k] images (tiny) ----------------
__global__ void prep_kernel(const float* __restrict__ W0, const float* __restrict__ W1,
                            const float* __restrict__ W2) {
    int i = blockIdx.x * blockDim.x + threadIdx.x;
    if (i >= 3 * DIM * DIM) return;
    int l = i >> 14;
    int e = i & 16383;
    int k = e >> 7, n = e & 127;
    const float* W = (l == 0) ? W0 : ((l == 1) ? W1 : W2);
    float w = W[e];  // W[k][n]
    __nv_bfloat16 hi = __float2bfloat16(w);
    __nv_bfloat16 lo = __float2bfloat16(w - __bfloat162float(hi));
    g_Whi[l][n * LDW + k] = hi;   // B operand stored [n][k]
    g_Wlo[l][n * LDW + k] = lo;
}

// ---------------- build adjacency (4 edges/thread); record duplicate edges -------------
__global__ void build_adj(const int* __restrict__ ei, int E) {
    int t = blockIdx.x * blockDim.x + threadIdx.x;
    if (t * 4 >= E) return;
    int4 r4 = ((const int4*)ei)[t];
    int4 c4 = ((const int4*)(ei + E))[t];
    int rs[4] = {r4.x, r4.y, r4.z, r4.w};
    int cs[4] = {c4.x, c4.y, c4.z, c4.w};
#pragma unroll
    for (int i = 0; i < 4; i++) {
        unsigned bit = 1u << (cs[i] & 31);
        unsigned old = atomicOr(&g_adj[rs[i] * NW + (cs[i] >> 5)], bit);
        if (old & bit) {
            int id = atomicAdd(&g_ndup, 1);
            if (id < 4096) { g_dupr[id] = rs[i]; g_dupc[id] = cs[i]; }
        }
    }
}

// ---------------- k_zero: reset adj + dup counter for the NEXT replay (off-path) -------
__global__ void k_zero() {
    int i = blockIdx.x * blockDim.x + threadIdx.x;   // 262144 threads x 2 uint4
    uint4 z = make_uint4(0u, 0u, 0u, 0u);
    ((uint4*)g_adj)[i * 2]     = z;
    ((uint4*)g_adj)[i * 2 + 1] = z;
    if (i == 0) g_ndup = 0;
}

// ---------------- fused MLP: 3x (128x128 GEMM + relu) + W3 matvec ----------------
#define ROWS_CTA 64
#define SM_W3   0                         // 128 f32
#define SM_ROWS 512                       // 64 f32 row accumulators
#define SM_AHI  768
#define SM_ALO  (SM_AHI + ROWS_CTA * LDW * 2)
#define SM_WHI  (SM_ALO + ROWS_CTA * LDW * 2)
#define SM_WLO  (SM_WHI + DIM * LDW * 2)
#define SM_MLP  (SM_WLO + DIM * LDW * 2)          // ~105 KB

__device__ __forceinline__ void store_split_u32(char* smem, int base, int row, int col,
                                                float x0, float x1) {
    __nv_bfloat16 h0 = __float2bfloat16(x0);
    __nv_bfloat16 h1 = __float2bfloat16(x1);
    *(uint32_t*)(smem + base + (row * LDW + col) * 2) =
        ((uint32_t)__bfloat16_as_ushort(h1) << 16) | (uint32_t)__bfloat16_as_ushort(h0);
}

__device__ __forceinline__ void copy_w_layer(char* smem, int l) {
    const uint4* sh = (const uint4*)g_Whi[l];
    const uint4* sl = (const uint4*)g_Wlo[l];
    uint4* dh = (uint4*)(smem + SM_WHI);
    uint4* dl = (uint4*)(smem + SM_WLO);
#pragma unroll 2
    for (int i = threadIdx.x; i < DIM * LDW * 2 / 16; i += 512) { dh[i] = sh[i]; dl[i] = sl[i]; }
}

__global__ void __launch_bounds__(512, 1)
mlp_kernel(const float* __restrict__ coeffs, const float* __restrict__ W3) {
    extern __shared__ char smem[];
    uint32_t sb = smem_u32(smem);
    int t = threadIdx.x;
    int w = t >> 5, lane = t & 31;
    int wm = w & 3, wn = w >> 2;
    int row0 = blockIdx.x * ROWS_CTA;

    if (t < 128) ((float*)(smem + SM_W3))[t] = W3[t];
    if (t < ROWS_CTA) ((float*)(smem + SM_ROWS))[t] = 0.0f;

    {
        int r = t >> 3, k0 = (t & 7) * 16;
        const float4* src = (const float4*)(coeffs + (size_t)(row0 + r) * DIM + k0);
#pragma unroll
        for (int i = 0; i < 4; i++) {
            float4 v = src[i];
            int c = k0 + i * 4;
            __nv_bfloat16 h0 = __float2bfloat16(v.x), h1 = __float2bfloat16(v.y);
            __nv_bfloat16 h2 = __float2bfloat16(v.z), h3 = __float2bfloat16(v.w);
            store_split_u32(smem, SM_AHI, r, c,     v.x, v.y);
            store_split_u32(smem, SM_AHI, r, c + 2, v.z, v.w);
            store_split_u32(smem, SM_ALO, r, c,
                            v.x - __bfloat162float(h0), v.y - __bfloat162float(h1));
            store_split_u32(smem, SM_ALO, r, c + 2,
                            v.z - __bfloat162float(h2), v.w - __bfloat162float(h3));
        }
    }
    copy_w_layer(smem, 0);
    __syncthreads();

    const float* W3s = (const float*)(smem + SM_W3);
    float* rows = (float*)(smem + SM_ROWS);
    int rowA = wm * 16;
    int nbase0 = wn * 32;

    for (int layer = 0; layer < 3; layer++) {
        float acc[4][4];
#pragma unroll
        for (int nt = 0; nt < 4; nt++)
#pragma unroll
            for (int q = 0; q < 4; q++) acc[nt][q] = 0.0f;

#pragma unroll 2
        for (int k = 0; k < 8; k++) {
            uint32_t ahi[4], alo[4];
            uint32_t aoff = ((rowA + (lane & 15)) * LDW + k * 16 + ((lane >> 4) * 8)) * 2;
            ldm_x4(ahi, sb + SM_AHI + aoff);
            ldm_x4(alo, sb + SM_ALO + aoff);
#pragma unroll
            for (int np = 0; np < 2; np++) {
                int nbase = nbase0 + np * 16;
                uint32_t boff = ((nbase + ((lane >> 3) & 1) * 8 + (lane & 7)) * LDW
                                 + k * 16 + ((lane >> 4) * 8)) * 2;
                uint32_t bhi[4], blo[4];
                ldm_x4(bhi, sb + SM_WHI + boff);
                ldm_x4(blo, sb + SM_WLO + boff);
                mma_bf16(acc[np * 2],     ahi, bhi[0], bhi[2]);
                mma_bf16(acc[np * 2],     ahi, blo[0], blo[2]);
                mma_bf16(acc[np * 2],     alo, bhi[0], bhi[2]);
                mma_bf16(acc[np * 2 + 1], ahi, bhi[1], bhi[3]);
                mma_bf16(acc[np * 2 + 1], ahi, blo[1], blo[3]);
                mma_bf16(acc[np * 2 + 1], alo, bhi[1], bhi[3]);
            }
        }
        __syncthreads();

        if (layer < 2) {
            int rw = rowA + (lane >> 2);
#pragma unroll
            for (int nt = 0; nt < 4; nt++) {
                int col = nbase0 + nt * 8 + (lane & 3) * 2;
                float f0 = fmaxf(acc[nt][0], 0.0f), f1 = fmaxf(acc[nt][1], 0.0f);
                float f2 = fmaxf(acc[nt][2], 0.0f), f3 = fmaxf(acc[nt][3], 0.0f);
                __nv_bfloat16 h0 = __float2bfloat16(f0), h1 = __float2bfloat16(f1);
                __nv_bfloat16 h2 = __float2bfloat16(f2), h3 = __float2bfloat16(f3);
                store_split_u32(smem, SM_AHI, rw,     col, f0, f1);
                store_split_u32(smem, SM_AHI, rw + 8, col, f2, f3);
                store_split_u32(smem, SM_ALO, rw,     col,
                                f0 - __bfloat162float(h0), f1 - __bfloat162float(h1));
                store_split_u32(smem, SM_ALO, rw + 8, col,
                                f2 - __bfloat162float(h2), f3 - __bfloat162float(h3));
            }
            copy_w_layer(smem, layer + 1);
            __syncthreads();
        } else {
            float p0 = 0.0f, p1 = 0.0f;
#pragma unroll
            for (int nt = 0; nt < 4; nt++) {
                int col = nbase0 + nt * 8 + (lane & 3) * 2;
                p0 += fmaxf(acc[nt][0], 0.0f) * W3s[col] + fmaxf(acc[nt][1], 0.0f) * W3s[col + 1];
                p1 += fmaxf(acc[nt][2], 0.0f) * W3s[col] + fmaxf(acc[nt][3], 0.0f) * W3s[col + 1];
            }
            p0 += __shfl_xor_sync(0xffffffffu, p0, 1);
            p0 += __shfl_xor_sync(0xffffffffu, p0, 2);
            p1 += __shfl_xor_sync(0xffffffffu, p1, 1);
            p1 += __shfl_xor_sync(0xffffffffu, p1, 2);
            if ((lane & 3) == 0) {
                atomicAdd(&rows[rowA + (lane >> 2)], p0);
                atomicAdd(&rows[rowA + (lane >> 2) + 8], p1);
            }
            __syncthreads();
            if (t < ROWS_CTA) g_ang[row0 + t] = rows[t];
        }
    }
}

// ---------------- full-row OR-gather over a neighbor list, unroll 4 ----------------
__device__ __forceinline__ void or_gather(const unsigned* __restrict__ src,
                                          const short* nlr, int n, int lane,
                                          uint4& A0, uint4& A1) {
    A0 = make_uint4(0u, 0u, 0u, 0u);
    A1 = make_uint4(0u, 0u, 0u, 0u);
    for (int kk = 0; kk < n; kk += 4) {
        uint4 x[4], y[4];
#pragma unroll
        for (int i = 0; i < 4; i++) {
            x[i] = make_uint4(0u, 0u, 0u, 0u);
            y[i] = make_uint4(0u, 0u, 0u, 0u);
            if (kk + i < n) {
                const uint4* p = (const uint4*)(src + (int)nlr[kk + i] * NW);
                x[i] = p[lane]; y[i] = p[lane + 32];
            }
        }
#pragma unroll
        for (int i = 0; i < 4; i++) {
            A0.x |= x[i].x; A0.y |= x[i].y; A0.z |= x[i].z; A0.w |= x[i].w;
            A1.x |= y[i].x; A1.y |= y[i].y; A1.z |= y[i].z; A1.w |= y[i].w;
        }
    }
}

// ---------------- k_p2: grid 1024 x 256, warp per row ----------------
__global__ void __launch_bounds__(256) k_p2() {
    __shared__ short nls[8][128];
    int t = threadIdx.x, lane = t & 31, w = t >> 5;
    int row = blockIdx.x * 8 + w;

    const uint4* a4 = (const uint4*)(g_adj + row * NW);
    uint4 m0 = a4[lane], m1 = a4[lane + 32];
    unsigned ws[8] = {m0.x, m0.y, m0.z, m0.w, m1.x, m1.y, m1.z, m1.w};
    int cnt = 0;
#pragma unroll
    for (int q = 0; q < 8; q++) cnt += __popc(ws[q]);
    int off = cnt;
#pragma unroll
    for (int o = 1; o < 32; o <<= 1) {
        int y = __shfl_up_sync(0xffffffffu, off, o);
        if (lane >= o) off += y;
    }
    int total = __shfl_sync(0xffffffffu, off, 31);
    off -= cnt;
    int n = total < 128 ? total : 128;
    if (lane == 0) g_ncap[row] = n;
    int id = off;
#pragma unroll
    for (int q = 0; q < 8; q++) {
        unsigned x = ws[q];
        int base = (((q < 4 ? lane : lane + 32) * 4) + (q & 3)) * 32;
        while (x) {
            int b = __ffs((int)x) - 1;
            x &= (x - 1);
            if (id < 128) { nls[w][id] = (short)(base + b); g_nl[row * 128 + id] = (short)(base + b); }
            id++;
        }
    }
    __syncwarp();
    uint4 A0, A1;
    or_gather(g_adj, nls[w], n, lane, A0, A1);
    ((uint4*)(g_P2 + row * NW))[lane]      = A0;
    ((uint4*)(g_P2 + row * NW))[lane + 32] = A1;
}

// ---------------- k_p3g: P3 = OR of P2 rows over nl (side stream, overlapped) ----------
__global__ void __launch_bounds__(256) k_p3g() {
    int t = threadIdx.x, lane = t & 31, w = t >> 5;
    int row = blockIdx.x * 8 + w;
    int n = g_ncap[row];
    uint4 A0, A1;
    or_gather(g_P2, g_nl + row * 128, n, lane, A0, A1);
    ((uint4*)(g_P3 + row * NW))[lane]      = A0;
    ((uint4*)(g_P3 + row * NW))[lane + 32] = A1;
}

// ---------------- k_s1: s1 = F1*(sum(ang[nbrs]) + dup contributions) ----------------
__global__ void k_s1() {
    int row = blockIdx.x * blockDim.x + threadIdx.x;
    if (row >= NN) return;
    int n = g_ncap[row];
    const short* nlr = g_nl + row * 128;
    float sa = 0.0f;
#pragma unroll 4
    for (int kk = 0; kk < n; kk++) sa += __ldg(&g_ang[(int)__ldg(&nlr[kk])]);
    int nd = g_ndup; if (nd > 4096) nd = 4096;
    for (int d = 0; d < nd; d++)           // uniform broadcast scan (~128 entries)
        if (g_dupr[d] == row) sa += __ldg(&g_ang[g_dupc[d]]);
    float s1 = F1 * sa;
    g_s1[row] = s1;
    g_enh1[row] = g_ang[row] + s1;
}

// ---------------- k_hop2: warp-per-row, sparse ffs dot (enh1 L2-resident) --------------
__global__ void __launch_bounds__(256) k_hop2() {
    int t = threadIdx.x, lane = t & 31, w = t >> 5;
    int row = blockIdx.x * 8 + w;
    const uint4* p4 = (const uint4*)(g_P2 + row * NW);
    uint4 m0 = p4[lane], m1 = p4[lane + 32];
    unsigned dw[8] = {m0.x, m0.y, m0.z, m0.w, m1.x, m1.y, m1.z, m1.w};
    float s = 0.0f;
#pragma unroll
    for (int q = 0; q < 8; q++) {
        unsigned x = dw[q];
        int base = (((q < 4 ? lane : lane + 32) * 4) + (q & 3)) * 32;
        while (x) {
            int b = __ffs((int)x) - 1;
            x &= (x - 1);
            s += __ldg(&g_enh1[base + b]);
        }
    }
#pragma unroll
    for (int o = 16; o; o >>= 1) s += __shfl_xor_sync(0xffffffffu, s, o);
    if (lane == 0) {
        float st2 = g_s1[row] + F2 * s;
        g_s2[row]   = st2;
        g_enh2[row] = g_enh1[row] + st2;
    }
}

// ---------------- k_dot: stream P3 rows + fp16 nibble LUT in smem (3 CTA/SM) -----------
#define DOT_SMEM (2048 * 16 * 2)     // 64 KB fp16 LUT
__global__ void __launch_bounds__(512, 3) k_dot(float* __restrict__ out) {
    extern __shared__ __half hlut[];
    int t = threadIdx.x, lane = t & 31, w = t >> 5;   // 16 warps

    for (int g = t; g < 2048; g += 512) {
        float f0 = __ldg(&g_enh2[g * 4]),     f1 = __ldg(&g_enh2[g * 4 + 1]);
        float f2 = __ldg(&g_enh2[g * 4 + 2]), f3 = __ldg(&g_enh2[g * 4 + 3]);
        __half* L = hlut + g * 16;
        int sw = g & 15;
#pragma unroll
        for (int n = 0; n < 16; n++) {
            float s = 0.0f;
            if (n & 1) s += f0;
            if (n & 2) s += f1;
            if (n & 4) s += f2;
            if (n & 8) s += f3;
            L[n ^ sw] = __float2half_rn(s);
        }
    }
    __syncthreads();

#pragma unroll
    for (int rr = 0; rr < 2; rr++) {               // 32 rows/block, grid 256
        int row = blockIdx.x * 32 + rr * 16 + w;
        const uint4* p4 = (const uint4*)(g_P3 + row * NW);   // coalesced stream
        uint4 m0 = p4[lane], m1 = p4[lane + 32];
        unsigned dw[8] = {m0.x, m0.y, m0.z, m0.w, m1.x, m1.y, m1.z, m1.w};
        float s = 0.0f;
#pragma unroll
        for (int q = 0; q < 8; q++) {
            unsigned x = dw[q];
            int wi = (q < 4 ? lane : lane + 32) * 4 + (q & 3);
#pragma unroll
            for (int hh = 0; hh < 8; hh++) {
                int hb = (hh + lane) & 7;              // lane-rotated order
                int g = wi * 8 + hb;
                unsigned nib = (x >> (4 * hb)) & 15u;
                s += __half2float(hlut[g * 16 + (nib ^ (unsigned)(g & 15))]);
            }
        }
#pragma unroll
        for (int o = 16; o; o >>= 1) s += __shfl_xor_sync(0xffffffffu, s, o);
        if (lane == 0) out[row] = __ldg(&g_enh2[row]) + __ldg(&g_s2[row]) + F3 * s;
    }
}

// ---------------- launch: MLP / P3-gather / next-replay zeroing on side stream ---------
extern "C" void kernel_launch(void* const* d_in, const int* in_sizes, int n_in,
                              void* d_out, int out_size) {
    const float* coeffs = (const float*)d_in[0];
    const float* W0 = (const float*)d_in[1];
    const float* W1 = (const float*)d_in[2];
    const float* W2 = (const float*)d_in[3];
    const float* W3 = (const float*)d_in[4];
    const int*   ei = (const int*)d_in[5];
    int E = in_sizes[5] / 2;
    float* out = (float*)d_out;

    static cudaStream_t s2 = nullptr;
    static cudaEvent_t evFork = nullptr, evJoin = nullptr;
    static cudaEvent_t evP2 = nullptr, evP3 = nullptr, evS1 = nullptr, evZero = nullptr;
    if (!s2) {
        cudaStreamCreateWithFlags(&s2, cudaStreamNonBlocking);
        cudaEventCreateWithFlags(&evFork, cudaEventDisableTiming);
        cudaEventCreateWithFlags(&evJoin, cudaEventDisableTiming);
        cudaEventCreateWithFlags(&evP2, cudaEventDisableTiming);
        cudaEventCreateWithFlags(&evP3, cudaEventDisableTiming);
        cudaEventCreateWithFlags(&evS1, cudaEventDisableTiming);
        cudaEventCreateWithFlags(&evZero, cudaEventDisableTiming);
        cudaFuncSetAttribute(mlp_kernel, cudaFuncAttributeMaxDynamicSharedMemorySize, SM_MLP);
        cudaFuncSetAttribute(k_dot, cudaFuncAttributeMaxDynamicSharedMemorySize, DOT_SMEM);
    }

    prep_kernel<<<192, 256>>>(W0, W1, W2);

    // fork: MLP on side stream, overlapped with adjacency build + P2 gather
    cudaEventRecord(evFork, 0);
    cudaStreamWaitEvent(s2, evFork, 0);
    mlp_kernel<<<NN / ROWS_CTA, 512, SM_MLP, s2>>>(coeffs, W3);
    cudaEventRecord(evJoin, s2);

    build_adj<<<(E / 4 + 255) / 256, 256>>>(ei, E);
    k_p2<<<NN / 8, 256>>>();
    cudaEventRecord(evP2, 0);

    // side stream: P3 gather (needs k_p2), overlapped with s1/hop2 chain
    cudaStreamWaitEvent(s2, evP2, 0);
    k_p3g<<<NN / 8, 256, 0, s2>>>();
    cudaEventRecord(evP3, s2);

    // main: angle-dependent chain (needs MLP)
    cudaStreamWaitEvent(0, evJoin, 0);
    k_s1<<<NN / 256, 256>>>();
    cudaEventRecord(evS1, 0);
    k_hop2<<<NN / 8, 256>>>();

    // side stream: zero adj + dup counter for next replay (after last readers)
    cudaStreamWaitEvent(s2, evS1, 0);
    k_zero<<<1024, 256, 0, s2>>>();
    cudaEventRecord(evZero, s2);

    // join: final dense dot, then join the zeroing before capture ends
    cudaStreamWaitEvent(0, evP3, 0);
    k_dot<<<NN / 32, 512, DOT_SMEM>>>(out);
    cudaStreamWaitEvent(0, evZero, 0);
}

// round 16
// speedup vs baseline: 1.5447x; 1.5447x over previous
#include <cuda_runtime.h>
#include <cuda_bf16.h>
#include <cuda_fp16.h>
#include <cstdint>

#define NN 8192        // nodes
#define NW 256         // mask words per row (8192/32)
#define DIM 128
#define LDW 136        // padded bf16 row stride (272 B) -> conflict-free ldmatrix

// exp(-ALPHA*k), ALPHA=2
#define F1 0.13533528323661270f
#define F2 0.018315638888734179f
#define F3 0.0024787521766663585f

// ---------------- scratch (static device globals; no allocation) ----------------
__device__ unsigned g_adj[NN * NW];   // 8 MB adjacency bitmask
__device__ unsigned g_P2[NN * NW];    // 8 MB bool(adj^2)
__device__ unsigned g_P3[NN * NW];    // 8 MB bool(adj^3)
__device__ float    g_ang[NN];
__device__ float    g_s1[NN];
__device__ float    g_enh1[NN];
__device__ float    g_s2[NN];
__device__ float    g_enh2[NN];
__device__ short    g_nl[NN * 128];   // 2 MB neighbor lists (capped 128)
__device__ int      g_ncap[NN];
__device__ int      g_ndup;
__device__ int      g_dupr[4096];
__device__ int      g_dupc[4096];
__device__ __align__(16) __nv_bfloat16 g_Whi[3][DIM * LDW];  // pre-split W, [n][k] padded
__device__ __align__(16) __nv_bfloat16 g_Wlo[3][DIM * LDW];

// ================= PTX helpers (family-agnostic ISA only) =================
__device__ __forceinline__ uint32_t smem_u32(const void* p) {
    uint32_t a;
    asm("{ .reg .u64 t; cvta.to.shared.u64 t, %1; cvt.u32.u64 %0, t; }" : "=r"(a) : "l"(p));
    return a;
}
__device__ __forceinline__ void ldm_x4(uint32_t* r, uint32_t addr) {
    asm volatile("ldmatrix.sync.aligned.m8n8.x4.shared.b16 {%0,%1,%2,%3}, [%4];"
                 : "=r"(r[0]), "=r"(r[1]), "=r"(r[2]), "=r"(r[3]) : "r"(addr));
}
__device__ __forceinline__ void mma_bf16(float* c, const uint32_t* a, uint32_t b0, uint32_t b1) {
    asm volatile(
        "mma.sync.aligned.m16n8k16.row.col.f32.bf16.bf16.f32 "
        "{%0,%1,%2,%3}, {%4,%5,%6,%7}, {%8,%9}, {%0,%1,%2,%3};"
        : "+f"(c[0]), "+f"(c[1]), "+f"(c[2]), "+f"(c[3])
        : "r"(a[0]), "r"(a[1]), "r"(a[2]), "r"(a[3]), "r"(b0), "r"(b1));
}

// ---------------- prep: zero adj + dup counter, split W into bf16 hi/lo images --------
__global__ void prep_kernel(const float* __restrict__ W0, const float* __restrict__ W1,
                            const float* __restrict__ W2) {
    int i = blockIdx.x * blockDim.x + threadIdx.x;     // 0..524287
    ((uint4*)g_adj)[i] = make_uint4(0u, 0u, 0u, 0u);   // 8 MB
    if (i == 0) g_ndup = 0;
    if (i < 3 * DIM * DIM) {
        int l = i >> 14;
        int e = i & 16383;
        int k = e >> 7, n = e & 127;
        const float* W = (l == 0) ? W0 : ((l == 1) ? W1 : W2);
        float w = W[e];  // W[k][n]
        __nv_bfloat16 hi = __float2bfloat16(w);
        __nv_bfloat16 lo = __float2bfloat16(w - __bfloat162float(hi));
        g_Whi[l][n * LDW + k] = hi;   // B operand stored [n][k]
        g_Wlo[l][n * LDW + k] = lo;
    }
}

// ---------------- build adjacency (4 edges/thread); record duplicate edges -------------
__global__ void build_adj(const int* __restrict__ ei, int E) {
    int t = blockIdx.x * blockDim.x + threadIdx.x;
    if (t * 4 >= E) return;
    int4 r4 = ((const int4*)ei)[t];
    int4 c4 = ((const int4*)(ei + E))[t];
    int rs[4] = {r4.x, r4.y, r4.z, r4.w};
    int cs[4] = {c4.x, c4.y, c4.z, c4.w};
#pragma unroll
    for (int i = 0; i < 4; i++) {
        unsigned bit = 1u << (cs[i] & 31);
        unsigned old = atomicOr(&g_adj[rs[i] * NW + (cs[i] >> 5)], bit);
        if (old & bit) {
            int id = atomicAdd(&g_ndup, 1);
            if (id < 4096) { g_dupr[id] = rs[i]; g_dupc[id] = cs[i]; }
        }
    }
}

// ---------------- fused MLP: 3x (128x128 GEMM + relu) + W3 matvec ----------------
#define ROWS_CTA 64
#define SM_W3   0                         // 128 f32
#define SM_ROWS 512                       // 64 f32 row accumulators
#define SM_AHI  768
#define SM_ALO  (SM_AHI + ROWS_CTA * LDW * 2)
#define SM_WHI  (SM_ALO + ROWS_CTA * LDW * 2)
#define SM_WLO  (SM_WHI + DIM * LDW * 2)
#define SM_MLP  (SM_WLO + DIM * LDW * 2)          // ~105 KB

__device__ __forceinline__ void store_split_u32(char* smem, int base, int row, int col,
                                                float x0, float x1) {
    __nv_bfloat16 h0 = __float2bfloat16(x0);
    __nv_bfloat16 h1 = __float2bfloat16(x1);
    *(uint32_t*)(smem + base + (row * LDW + col) * 2) =
        ((uint32_t)__bfloat16_as_ushort(h1) << 16) | (uint32_t)__bfloat16_as_ushort(h0);
}

__device__ __forceinline__ void copy_w_layer(char* smem, int l) {
    const uint4* sh = (const uint4*)g_Whi[l];
    const uint4* sl = (const uint4*)g_Wlo[l];
    uint4* dh = (uint4*)(smem + SM_WHI);
    uint4* dl = (uint4*)(smem + SM_WLO);
#pragma unroll 2
    for (int i = threadIdx.x; i < DIM * LDW * 2 / 16; i += 512) { dh[i] = sh[i]; dl[i] = sl[i]; }
}

__global__ void __launch_bounds__(512, 1)
mlp_kernel(const float* __restrict__ coeffs, const float* __restrict__ W3) {
    extern __shared__ char smem[];
    uint32_t sb = smem_u32(smem);
    int t = threadIdx.x;
    int w = t >> 5, lane = t & 31;
    int wm = w & 3, wn = w >> 2;
    int row0 = blockIdx.x * ROWS_CTA;

    if (t < 128) ((float*)(smem + SM_W3))[t] = W3[t];
    if (t < ROWS_CTA) ((float*)(smem + SM_ROWS))[t] = 0.0f;

    {
        int r = t >> 3, k0 = (t & 7) * 16;
        const float4* src = (const float4*)(coeffs + (size_t)(row0 + r) * DIM + k0);
#pragma unroll
        for (int i = 0; i < 4; i++) {
            float4 v = src[i];
            int c = k0 + i * 4;
            __nv_bfloat16 h0 = __float2bfloat16(v.x), h1 = __float2bfloat16(v.y);
            __nv_bfloat16 h2 = __float2bfloat16(v.z), h3 = __float2bfloat16(v.w);
            store_split_u32(smem, SM_AHI, r, c,     v.x, v.y);
            store_split_u32(smem, SM_AHI, r, c + 2, v.z, v.w);
            store_split_u32(smem, SM_ALO, r, c,
                            v.x - __bfloat162float(h0), v.y - __bfloat162float(h1));
            store_split_u32(smem, SM_ALO, r, c + 2,
                            v.z - __bfloat162float(h2), v.w - __bfloat162float(h3));
        }
    }
    copy_w_layer(smem, 0);
    __syncthreads();

    const float* W3s = (const float*)(smem + SM_W3);
    float* rows = (float*)(smem + SM_ROWS);
    int rowA = wm * 16;
    int nbase0 = wn * 32;

    for (int layer = 0; layer < 3; layer++) {
        float acc[4][4];
#pragma unroll
        for (int nt = 0; nt < 4; nt++)
#pragma unroll
            for (int q = 0; q < 4; q++) acc[nt][q] = 0.0f;

#pragma unroll 2
        for (int k = 0; k < 8; k++) {
            uint32_t ahi[4], alo[4];
            uint32_t aoff = ((rowA + (lane & 15)) * LDW + k * 16 + ((lane >> 4) * 8)) * 2;
            ldm_x4(ahi, sb + SM_AHI + aoff);
            ldm_x4(alo, sb + SM_ALO + aoff);
#pragma unroll
            for (int np = 0; np < 2; np++) {
                int nbase = nbase0 + np * 16;
                uint32_t boff = ((nbase + ((lane >> 3) & 1) * 8 + (lane & 7)) * LDW
                                 + k * 16 + ((lane >> 4) * 8)) * 2;
                uint32_t bhi[4], blo[4];
                ldm_x4(bhi, sb + SM_WHI + boff);
                ldm_x4(blo, sb + SM_WLO + boff);
                mma_bf16(acc[np * 2],     ahi, bhi[0], bhi[2]);
                mma_bf16(acc[np * 2],     ahi, blo[0], blo[2]);
                mma_bf16(acc[np * 2],     alo, bhi[0], bhi[2]);
                mma_bf16(acc[np * 2 + 1], ahi, bhi[1], bhi[3]);
                mma_bf16(acc[np * 2 + 1], ahi, blo[1], blo[3]);
                mma_bf16(acc[np * 2 + 1], alo, bhi[1], bhi[3]);
            }
        }
        __syncthreads();

        if (layer < 2) {
            int rw = rowA + (lane >> 2);
#pragma unroll
            for (int nt = 0; nt < 4; nt++) {
                int col = nbase0 + nt * 8 + (lane & 3) * 2;
                float f0 = fmaxf(acc[nt][0], 0.0f), f1 = fmaxf(acc[nt][1], 0.0f);
                float f2 = fmaxf(acc[nt][2], 0.0f), f3 = fmaxf(acc[nt][3], 0.0f);
                __nv_bfloat16 h0 = __float2bfloat16(f0), h1 = __float2bfloat16(f1);
                __nv_bfloat16 h2 = __float2bfloat16(f2), h3 = __float2bfloat16(f3);
                store_split_u32(smem, SM_AHI, rw,     col, f0, f1);
                store_split_u32(smem, SM_AHI, rw + 8, col, f2, f3);
                store_split_u32(smem, SM_ALO, rw,     col,
                                f0 - __bfloat162float(h0), f1 - __bfloat162float(h1));
                store_split_u32(smem, SM_ALO, rw + 8, col,
                                f2 - __bfloat162float(h2), f3 - __bfloat162float(h3));
            }
            copy_w_layer(smem, layer + 1);
            __syncthreads();
        } else {
            float p0 = 0.0f, p1 = 0.0f;
#pragma unroll
            for (int nt = 0; nt < 4; nt++) {
                int col = nbase0 + nt * 8 + (lane & 3) * 2;
                p0 += fmaxf(acc[nt][0], 0.0f) * W3s[col] + fmaxf(acc[nt][1], 0.0f) * W3s[col + 1];
                p1 += fmaxf(acc[nt][2], 0.0f) * W3s[col] + fmaxf(acc[nt][3], 0.0f) * W3s[col + 1];
            }
            p0 += __shfl_xor_sync(0xffffffffu, p0, 1);
            p0 += __shfl_xor_sync(0xffffffffu, p0, 2);
            p1 += __shfl_xor_sync(0xffffffffu, p1, 1);
            p1 += __shfl_xor_sync(0xffffffffu, p1, 2);
            if ((lane & 3) == 0) {
                atomicAdd(&rows[rowA + (lane >> 2)], p0);
                atomicAdd(&rows[rowA + (lane >> 2) + 8], p1);
            }
            __syncthreads();
            if (t < ROWS_CTA) g_ang[row0 + t] = rows[t];
        }
    }
}

// ---------------- full-row OR-gather over a neighbor list, unroll 4 ----------------
__device__ __forceinline__ void or_gather(const unsigned* __restrict__ src,
                                          const short* nlr, int n, int lane,
                                          uint4& A0, uint4& A1) {
    A0 = make_uint4(0u, 0u, 0u, 0u);
    A1 = make_uint4(0u, 0u, 0u, 0u);
    for (int kk = 0; kk < n; kk += 4) {
        uint4 x[4], y[4];
#pragma unroll
        for (int i = 0; i < 4; i++) {
            x[i] = make_uint4(0u, 0u, 0u, 0u);
            y[i] = make_uint4(0u, 0u, 0u, 0u);
            if (kk + i < n) {
                const uint4* p = (const uint4*)(src + (int)nlr[kk + i] * NW);
                x[i] = p[lane]; y[i] = p[lane + 32];
            }
        }
#pragma unroll
        for (int i = 0; i < 4; i++) {
            A0.x |= x[i].x; A0.y |= x[i].y; A0.z |= x[i].z; A0.w |= x[i].w;
            A1.x |= y[i].x; A1.y |= y[i].y; A1.z |= y[i].z; A1.w |= y[i].w;
        }
    }
}

// ---------------- k_p2: grid 1024 x 256, warp per row ----------------
__global__ void __launch_bounds__(256) k_p2() {
    __shared__ short nls[8][128];
    int t = threadIdx.x, lane = t & 31, w = t >> 5;
    int row = blockIdx.x * 8 + w;

    const uint4* a4 = (const uint4*)(g_adj + row * NW);
    uint4 m0 = a4[lane], m1 = a4[lane + 32];
    unsigned ws[8] = {m0.x, m0.y, m0.z, m0.w, m1.x, m1.y, m1.z, m1.w};
    int cnt = 0;
#pragma unroll
    for (int q = 0; q < 8; q++) cnt += __popc(ws[q]);
    int off = cnt;
#pragma unroll
    for (int o = 1; o < 32; o <<= 1) {
        int y = __shfl_up_sync(0xffffffffu, off, o);
        if (lane >= o) off += y;
    }
    int total = __shfl_sync(0xffffffffu, off, 31);
    off -= cnt;
    int n = total < 128 ? total : 128;
    if (lane == 0) g_ncap[row] = n;
    int id = off;
#pragma unroll
    for (int q = 0; q < 8; q++) {
        unsigned x = ws[q];
        int base = (((q < 4 ? lane : lane + 32) * 4) + (q & 3)) * 32;
        while (x) {
            int b = __ffs((int)x) - 1;
            x &= (x - 1);
            if (id < 128) { nls[w][id] = (short)(base + b); g_nl[row * 128 + id] = (short)(base + b); }
            id++;
        }
    }
    __syncwarp();
    uint4 A0, A1;
    or_gather(g_adj, nls[w], n, lane, A0, A1);
    ((uint4*)(g_P2 + row * NW))[lane]      = A0;
    ((uint4*)(g_P2 + row * NW))[lane + 32] = A1;
}

// ---------------- k_p3g: P3 = OR of P2 rows over nl (side stream, overlapped) ----------
__global__ void __launch_bounds__(256) k_p3g() {
    int t = threadIdx.x, lane = t & 31, w = t >> 5;
    int row = blockIdx.x * 8 + w;
    int n = g_ncap[row];
    uint4 A0, A1;
    or_gather(g_P2, g_nl + row * 128, n, lane, A0, A1);
    ((uint4*)(g_P3 + row * NW))[lane]      = A0;
    ((uint4*)(g_P3 + row * NW))[lane + 32] = A1;
}

// ---------------- k_s1: s1 = F1*(sum(ang[nbrs]) + dup contributions) ----------------
__global__ void k_s1() {
    int row = blockIdx.x * blockDim.x + threadIdx.x;
    if (row >= NN) return;
    int n = g_ncap[row];
    const short* nlr = g_nl + row * 128;
    float sa = 0.0f;
#pragma unroll 4
    for (int kk = 0; kk < n; kk++) sa += __ldg(&g_ang[(int)__ldg(&nlr[kk])]);
    int nd = g_ndup; if (nd > 4096) nd = 4096;
    for (int d = 0; d < nd; d++)           // uniform broadcast scan (~128 entries)
        if (g_dupr[d] == row) sa += __ldg(&g_ang[g_dupc[d]]);
    float s1 = F1 * sa;
    g_s1[row] = s1;
    g_enh1[row] = g_ang[row] + s1;
}

// ---------------- k_hop2: warp-per-row, sparse ffs dot (enh1 L2-resident) --------------
__global__ void __launch_bounds__(256) k_hop2() {
    int t = threadIdx.x, lane = t & 31, w = t >> 5;
    int row = blockIdx.x * 8 + w;
    const uint4* p4 = (const uint4*)(g_P2 + row * NW);
    uint4 m0 = p4[lane], m1 = p4[lane + 32];
    unsigned dw[8] = {m0.x, m0.y, m0.z, m0.w, m1.x, m1.y, m1.z, m1.w};
    float s = 0.0f;
#pragma unroll
    for (int q = 0; q < 8; q++) {
        unsigned x = dw[q];
        int base = (((q < 4 ? lane : lane + 32) * 4) + (q & 3)) * 32;
        while (x) {
            int b = __ffs((int)x) - 1;
            x &= (x - 1);
            s += __ldg(&g_enh1[base + b]);
        }
    }
#pragma unroll
    for (int o = 16; o; o >>= 1) s += __shfl_xor_sync(0xffffffffu, s, o);
    if (lane == 0) {
        float st2 = g_s1[row] + F2 * s;
        g_s2[row]   = st2;
        g_enh2[row] = g_enh1[row] + st2;
    }
}

// ---------------- k_dot: stream P3 rows + fp16 nibble LUT in smem (3 CTA/SM) -----------
#define DOT_SMEM (2048 * 16 * 2)     // 64 KB fp16 LUT
__global__ void __launch_bounds__(512, 3) k_dot(float* __restrict__ out) {
    extern __shared__ __half hlut[];
    int t = threadIdx.x, lane = t & 31, w = t >> 5;   // 16 warps

    for (int g = t; g < 2048; g += 512) {
        float f0 = __ldg(&g_enh2[g * 4]),     f1 = __ldg(&g_enh2[g * 4 + 1]);
        float f2 = __ldg(&g_enh2[g * 4 + 2]), f3 = __ldg(&g_enh2[g * 4 + 3]);
        __half* L = hlut + g * 16;
        int sw = g & 15;
#pragma unroll
        for (int n = 0; n < 16; n++) {
            float s = 0.0f;
            if (n & 1) s += f0;
            if (n & 2) s += f1;
            if (n & 4) s += f2;
            if (n & 8) s += f3;
            L[n ^ sw] = __float2half_rn(s);
        }
    }
    __syncthreads();

#pragma unroll
    for (int rr = 0; rr < 2; rr++) {               // 32 rows/block, grid 256
        int row = blockIdx.x * 32 + rr * 16 + w;
        const uint4* p4 = (const uint4*)(g_P3 + row * NW);   // coalesced stream
        uint4 m0 = p4[lane], m1 = p4[lane + 32];
        unsigned dw[8] = {m0.x, m0.y, m0.z, m0.w, m1.x, m1.y, m1.z, m1.w};
        float s = 0.0f;
#pragma unroll
        for (int q = 0; q < 8; q++) {
            unsigned x = dw[q];
            int wi = (q < 4 ? lane : lane + 32) * 4 + (q & 3);
#pragma unroll
            for (int hh = 0; hh < 8; hh++) {
                int hb = (hh + lane) & 7;              // lane-rotated order
                int g = wi * 8 + hb;
                unsigned nib = (x >> (4 * hb)) & 15u;
                s += __half2float(hlut[g * 16 + (nib ^ (unsigned)(g & 15))]);
            }
        }
#pragma unroll
        for (int o = 16; o; o >>= 1) s += __shfl_xor_sync(0xffffffffu, s, o);
        if (lane == 0) out[row] = __ldg(&g_enh2[row]) + __ldg(&g_s2[row]) + F3 * s;
    }
}

// ---------------- launch: MLP + P3-gather overlapped on a side stream ----------------
extern "C" void kernel_launch(void* const* d_in, const int* in_sizes, int n_in,
                              void* d_out, int out_size) {
    const float* coeffs = (const float*)d_in[0];
    const float* W0 = (const float*)d_in[1];
    const float* W1 = (const float*)d_in[2];
    const float* W2 = (const float*)d_in[3];
    const float* W3 = (const float*)d_in[4];
    const int*   ei = (const int*)d_in[5];
    int E = in_sizes[5] / 2;
    float* out = (float*)d_out;

    static cudaStream_t s2 = nullptr;
    static cudaEvent_t evFork = nullptr, evJoin = nullptr, evFork2 = nullptr, evJoin2 = nullptr;
    if (!s2) {
        cudaStreamCreateWithFlags(&s2, cudaStreamNonBlocking);
        cudaEventCreateWithFlags(&evFork, cudaEventDisableTiming);
        cudaEventCreateWithFlags(&evJoin, cudaEventDisableTiming);
        cudaEventCreateWithFlags(&evFork2, cudaEventDisableTiming);
        cudaEventCreateWithFlags(&evJoin2, cudaEventDisableTiming);
        cudaFuncSetAttribute(mlp_kernel, cudaFuncAttributeMaxDynamicSharedMemorySize, SM_MLP);
        cudaFuncSetAttribute(k_dot, cudaFuncAttributeMaxDynamicSharedMemorySize, DOT_SMEM);
    }

    prep_kernel<<<2048, 256>>>(W0, W1, W2);

    // fork 1: MLP on side stream, overlapped with adjacency build + P2 gather
    cudaEventRecord(evFork, 0);
    cudaStreamWaitEvent(s2, evFork, 0);
    mlp_kernel<<<NN / ROWS_CTA, 512, SM_MLP, s2>>>(coeffs, W3);
    cudaEventRecord(evJoin, s2);

    build_adj<<<(E / 4 + 255) / 256, 256>>>(ei, E);
    k_p2<<<NN / 8, 256>>>();

    // fork 2: P3 gather on side stream (depends only on k_p2), overlapped with hop chain
    cudaEventRecord(evFork2, 0);
    cudaStreamWaitEvent(s2, evFork2, 0);
    k_p3g<<<NN / 8, 256, 0, s2>>>();
    cudaEventRecord(evJoin2, s2);

    // main: angle-dependent chain (needs MLP)
    cudaStreamWaitEvent(0, evJoin, 0);
    k_s1<<<NN / 256, 256>>>();
    k_hop2<<<NN / 8, 256>>>();

    // join: final dense dot
    cudaStreamWaitEvent(0, evJoin2, 0);
    k_dot<<<NN / 32, 512, DOT_SMEM>>>(out);
}

// round 17
// speedup vs baseline: 1.6509x; 1.0687x over previous
#include <cuda_runtime.h>
#include <cuda_bf16.h>
#include <cuda_fp16.h>
#include <cstdint>

#define NN 8192        // nodes
#define NW 256         // mask words per row (8192/32)
#define DIM 128
#define LDW 136        // padded bf16 row stride (272 B) -> conflict-free ldmatrix

// exp(-ALPHA*k), ALPHA=2
#define F1 0.13533528323661270f
#define F2 0.018315638888734179f
#define F3 0.0024787521766663585f

// ---------------- scratch (static device globals; no allocation) ----------------
__device__ unsigned g_adj[NN * NW];   // 8 MB adjacency bitmask
__device__ unsigned g_P2[NN * NW];    // 8 MB bool(adj^2)
__device__ unsigned g_P3[NN * NW];    // 8 MB bool(adj^3)
__device__ float    g_ang[NN];
__device__ float    g_s1[NN];
__device__ float    g_enh1[NN];
__device__ float    g_s2[NN];
__device__ float    g_enh2[NN];
__device__ short    g_nl[NN * 128];   // 2 MB neighbor lists (capped 128)
__device__ int      g_ncap[NN];
__device__ int      g_ndup;
__device__ int      g_dupr[4096];
__device__ int      g_dupc[4096];
__device__ __align__(16) __nv_bfloat16 g_Whi[3][DIM * LDW];  // pre-split W, [n][k] padded
__device__ __align__(16) __nv_bfloat16 g_Wlo[3][DIM * LDW];

// ================= PTX helpers (family-agnostic ISA only) =================
__device__ __forceinline__ uint32_t smem_u32(const void* p) {
    uint32_t a;
    asm("{ .reg .u64 t; cvta.to.shared.u64 t, %1; cvt.u32.u64 %0, t; }" : "=r"(a) : "l"(p));
    return a;
}
__device__ __forceinline__ void ldm_x4(uint32_t* r, uint32_t addr) {
    asm volatile("ldmatrix.sync.aligned.m8n8.x4.shared.b16 {%0,%1,%2,%3}, [%4];"
                 : "=r"(r[0]), "=r"(r[1]), "=r"(r[2]), "=r"(r[3]) : "r"(addr));
}
__device__ __forceinline__ void mma_bf16(float* c, const uint32_t* a, uint32_t b0, uint32_t b1) {
    asm volatile(
        "mma.sync.aligned.m16n8k16.row.col.f32.bf16.bf16.f32 "
        "{%0,%1,%2,%3}, {%4,%5,%6,%7}, {%8,%9}, {%0,%1,%2,%3};"
        : "+f"(c[0]), "+f"(c[1]), "+f"(c[2]), "+f"(c[3])
        : "r"(a[0]), "r"(a[1]), "r"(a[2]), "r"(a[3]), "r"(b0), "r"(b1));
}

// ---------------- prep: zero adj + s1, split W into bf16 hi/lo [n][k] images ----------
__global__ void prep_kernel(const float* __restrict__ W0, const float* __restrict__ W1,
                            const float* __restrict__ W2) {
    int i = blockIdx.x * blockDim.x + threadIdx.x;     // 0..524287
    ((uint4*)g_adj)[i] = make_uint4(0u, 0u, 0u, 0u);   // 8 MB
    if (i == 0) g_ndup = 0;
    if (i < NN) g_s1[i] = 0.0f;
    if (i < 3 * DIM * DIM) {
        int l = i >> 14;
        int e = i & 16383;
        int k = e >> 7, n = e & 127;
        const float* W = (l == 0) ? W0 : ((l == 1) ? W1 : W2);
        float w = W[e];  // W[k][n]
        __nv_bfloat16 hi = __float2bfloat16(w);
        __nv_bfloat16 lo = __float2bfloat16(w - __bfloat162float(hi));
        g_Whi[l][n * LDW + k] = hi;   // B operand stored [n][k]
        g_Wlo[l][n * LDW + k] = lo;
    }
}

// ---------------- build adjacency; record duplicate edges via atomicOr old value -------
__global__ void build_adj(const int* __restrict__ ei, int E) {
    int t = blockIdx.x * blockDim.x + threadIdx.x;
    if (t >= E) return;
    int r = ei[t];
    int c = ei[E + t];
    unsigned bit = 1u << (c & 31);
    unsigned old = atomicOr(&g_adj[r * NW + (c >> 5)], bit);
    if (old & bit) {
        int id = atomicAdd(&g_ndup, 1);
        if (id < 4096) { g_dupr[id] = r; g_dupc[id] = c; }
    }
}

// ---------------- fused MLP: 3x (128x128 GEMM + relu) + W3 matvec ----------------
#define ROWS_CTA 64
#define SM_W3   0                         // 128 f32
#define SM_ROWS 512                       // 64 f32 row accumulators
#define SM_AHI  768
#define SM_ALO  (SM_AHI + ROWS_CTA * LDW * 2)
#define SM_WHI  (SM_ALO + ROWS_CTA * LDW * 2)
#define SM_WLO  (SM_WHI + DIM * LDW * 2)
#define SM_MLP  (SM_WLO + DIM * LDW * 2)          // ~105 KB

__device__ __forceinline__ void store_split_u32(char* smem, int base, int row, int col,
                                                float x0, float x1) {
    __nv_bfloat16 h0 = __float2bfloat16(x0);
    __nv_bfloat16 h1 = __float2bfloat16(x1);
    *(uint32_t*)(smem + base + (row * LDW + col) * 2) =
        ((uint32_t)__bfloat16_as_ushort(h1) << 16) | (uint32_t)__bfloat16_as_ushort(h0);
}

__device__ __forceinline__ void copy_w_layer(char* smem, int l) {
    const uint4* sh = (const uint4*)g_Whi[l];
    const uint4* sl = (const uint4*)g_Wlo[l];
    uint4* dh = (uint4*)(smem + SM_WHI);
    uint4* dl = (uint4*)(smem + SM_WLO);
#pragma unroll 2
    for (int i = threadIdx.x; i < DIM * LDW * 2 / 16; i += 512) { dh[i] = sh[i]; dl[i] = sl[i]; }
}

__global__ void __launch_bounds__(512, 1)
mlp_kernel(const float* __restrict__ coeffs, const float* __restrict__ W3) {
    extern __shared__ char smem[];
    uint32_t sb = smem_u32(smem);
    int t = threadIdx.x;
    int w = t >> 5, lane = t & 31;
    int wm = w & 3, wn = w >> 2;
    int row0 = blockIdx.x * ROWS_CTA;

    if (t < 128) ((float*)(smem + SM_W3))[t] = W3[t];
    if (t < ROWS_CTA) ((float*)(smem + SM_ROWS))[t] = 0.0f;

    {
        int r = t >> 3, k0 = (t & 7) * 16;
        const float4* src = (const float4*)(coeffs + (size_t)(row0 + r) * DIM + k0);
#pragma unroll
        for (int i = 0; i < 4; i++) {
            float4 v = src[i];
            int c = k0 + i * 4;
            __nv_bfloat16 h0 = __float2bfloat16(v.x), h1 = __float2bfloat16(v.y);
            __nv_bfloat16 h2 = __float2bfloat16(v.z), h3 = __float2bfloat16(v.w);
            store_split_u32(smem, SM_AHI, r, c,     v.x, v.y);
            store_split_u32(smem, SM_AHI, r, c + 2, v.z, v.w);
            store_split_u32(smem, SM_ALO, r, c,
                            v.x - __bfloat162float(h0), v.y - __bfloat162float(h1));
            store_split_u32(smem, SM_ALO, r, c + 2,
                            v.z - __bfloat162float(h2), v.w - __bfloat162float(h3));
        }
    }
    copy_w_layer(smem, 0);
    __syncthreads();

    const float* W3s = (const float*)(smem + SM_W3);
    float* rows = (float*)(smem + SM_ROWS);
    int rowA = wm * 16;
    int nbase0 = wn * 32;

    for (int layer = 0; layer < 3; layer++) {
        float acc[4][4];
#pragma unroll
        for (int nt = 0; nt < 4; nt++)
#pragma unroll
            for (int q = 0; q < 4; q++) acc[nt][q] = 0.0f;

#pragma unroll 2
        for (int k = 0; k < 8; k++) {
            uint32_t ahi[4], alo[4];
            uint32_t aoff = ((rowA + (lane & 15)) * LDW + k * 16 + ((lane >> 4) * 8)) * 2;
            ldm_x4(ahi, sb + SM_AHI + aoff);
            ldm_x4(alo, sb + SM_ALO + aoff);
#pragma unroll
            for (int np = 0; np < 2; np++) {
                int nbase = nbase0 + np * 16;
                uint32_t boff = ((nbase + ((lane >> 3) & 1) * 8 + (lane & 7)) * LDW
                                 + k * 16 + ((lane >> 4) * 8)) * 2;
                uint32_t bhi[4], blo[4];
                ldm_x4(bhi, sb + SM_WHI + boff);
                ldm_x4(blo, sb + SM_WLO + boff);
                mma_bf16(acc[np * 2],     ahi, bhi[0], bhi[2]);
                mma_bf16(acc[np * 2],     ahi, blo[0], blo[2]);
                mma_bf16(acc[np * 2],     alo, bhi[0], bhi[2]);
                mma_bf16(acc[np * 2 + 1], ahi, bhi[1], bhi[3]);
                mma_bf16(acc[np * 2 + 1], ahi, blo[1], blo[3]);
                mma_bf16(acc[np * 2 + 1], alo, bhi[1], bhi[3]);
            }
        }
        __syncthreads();

        if (layer < 2) {
            int rw = rowA + (lane >> 2);
#pragma unroll
            for (int nt = 0; nt < 4; nt++) {
                int col = nbase0 + nt * 8 + (lane & 3) * 2;
                float f0 = fmaxf(acc[nt][0], 0.0f), f1 = fmaxf(acc[nt][1], 0.0f);
                float f2 = fmaxf(acc[nt][2], 0.0f), f3 = fmaxf(acc[nt][3], 0.0f);
                __nv_bfloat16 h0 = __float2bfloat16(f0), h1 = __float2bfloat16(f1);
                __nv_bfloat16 h2 = __float2bfloat16(f2), h3 = __float2bfloat16(f3);
                store_split_u32(smem, SM_AHI, rw,     col, f0, f1);
                store_split_u32(smem, SM_AHI, rw + 8, col, f2, f3);
                store_split_u32(smem, SM_ALO, rw,     col,
                                f0 - __bfloat162float(h0), f1 - __bfloat162float(h1));
                store_split_u32(smem, SM_ALO, rw + 8, col,
                                f2 - __bfloat162float(h2), f3 - __bfloat162float(h3));
            }
            copy_w_layer(smem, layer + 1);
            __syncthreads();
        } else {
            float p0 = 0.0f, p1 = 0.0f;
#pragma unroll
            for (int nt = 0; nt < 4; nt++) {
                int col = nbase0 + nt * 8 + (lane & 3) * 2;
                p0 += fmaxf(acc[nt][0], 0.0f) * W3s[col] + fmaxf(acc[nt][1], 0.0f) * W3s[col + 1];
                p1 += fmaxf(acc[nt][2], 0.0f) * W3s[col] + fmaxf(acc[nt][3], 0.0f) * W3s[col + 1];
            }
            p0 += __shfl_xor_sync(0xffffffffu, p0, 1);
            p0 += __shfl_xor_sync(0xffffffffu, p0, 2);
            p1 += __shfl_xor_sync(0xffffffffu, p1, 1);
            p1 += __shfl_xor_sync(0xffffffffu, p1, 2);
            if ((lane & 3) == 0) {
                atomicAdd(&rows[rowA + (lane >> 2)], p0);
                atomicAdd(&rows[rowA + (lane >> 2) + 8], p1);
            }
            __syncthreads();
            if (t < ROWS_CTA) g_ang[row0 + t] = rows[t];
        }
    }
}

// ---------------- full-row OR-gather over a neighbor list, unroll 4 ----------------
__device__ __forceinline__ void or_gather(const unsigned* __restrict__ src,
                                          const short* nlr, int n, int lane,
                                          uint4& A0, uint4& A1) {
    A0 = make_uint4(0u, 0u, 0u, 0u);
    A1 = make_uint4(0u, 0u, 0u, 0u);
    for (int kk = 0; kk < n; kk += 4) {
        uint4 x[4], y[4];
#pragma unroll
        for (int i = 0; i < 4; i++) {
            x[i] = make_uint4(0u, 0u, 0u, 0u);
            y[i] = make_uint4(0u, 0u, 0u, 0u);
            if (kk + i < n) {
                const uint4* p = (const uint4*)(src + (int)nlr[kk + i] * NW);
                x[i] = p[lane]; y[i] = p[lane + 32];
            }
        }
#pragma unroll
        for (int i = 0; i < 4; i++) {
            A0.x |= x[i].x; A0.y |= x[i].y; A0.z |= x[i].z; A0.w |= x[i].w;
            A1.x |= y[i].x; A1.y |= y[i].y; A1.z |= y[i].z; A1.w |= y[i].w;
        }
    }
}

// ---------------- k_p2: grid 1024 x 256, warp per row ----------------
__global__ void __launch_bounds__(256) k_p2() {
    __shared__ short nls[8][128];
    int t = threadIdx.x, lane = t & 31, w = t >> 5;
    int row = blockIdx.x * 8 + w;

    const uint4* a4 = (const uint4*)(g_adj + row * NW);
    uint4 m0 = a4[lane], m1 = a4[lane + 32];
    unsigned ws[8] = {m0.x, m0.y, m0.z, m0.w, m1.x, m1.y, m1.z, m1.w};
    int cnt = 0;
#pragma unroll
    for (int q = 0; q < 8; q++) cnt += __popc(ws[q]);
    int off = cnt;
#pragma unroll
    for (int o = 1; o < 32; o <<= 1) {
        int y = __shfl_up_sync(0xffffffffu, off, o);
        if (lane >= o) off += y;
    }
    int total = __shfl_sync(0xffffffffu, off, 31);
    off -= cnt;
    int n = total < 128 ? total : 128;
    if (lane == 0) g_ncap[row] = n;
    int id = off;
#pragma unroll
    for (int q = 0; q < 8; q++) {
        unsigned x = ws[q];
        int base = (((q < 4 ? lane : lane + 32) * 4) + (q & 3)) * 32;
        while (x) {
            int b = __ffs((int)x) - 1;
            x &= (x - 1);
            if (id < 128) { nls[w][id] = (short)(base + b); g_nl[row * 128 + id] = (short)(base + b); }
            id++;
        }
    }
    __syncwarp();
    uint4 A0, A1;
    or_gather(g_adj, nls[w], n, lane, A0, A1);
    ((uint4*)(g_P2 + row * NW))[lane]      = A0;
    ((uint4*)(g_P2 + row * NW))[lane + 32] = A1;
}

// ---------------- k_p3g: P3 = OR of P2 rows over nl (side stream, overlapped) ----------
__global__ void __launch_bounds__(256) k_p3g() {
    int t = threadIdx.x, lane = t & 31, w = t >> 5;
    int row = blockIdx.x * 8 + w;
    int n = g_ncap[row];
    uint4 A0, A1;
    or_gather(g_P2, g_nl + row * 128, n, lane, A0, A1);
    ((uint4*)(g_P3 + row * NW))[lane]      = A0;
    ((uint4*)(g_P3 + row * NW))[lane + 32] = A1;
}

// ---------------- k_dup: duplicate-edge hop-1 contributions (needs ang) ----------------
__global__ void k_dup() {
    int d = blockIdx.x * blockDim.x + threadIdx.x;
    int nd = g_ndup; if (nd > 4096) nd = 4096;
    if (d < nd) atomicAdd(&g_s1[g_dupr[d]], F1 * g_ang[g_dupc[d]]);
}

// ---------------- k_s1: s1 += F1*sum(ang[nbrs]); enh1 = ang + s1 (256 x 32) ------------
__global__ void k_s1() {
    int row = blockIdx.x * blockDim.x + threadIdx.x;
    if (row >= NN) return;
    int n = g_ncap[row];
    const short* nlr = g_nl + row * 128;
    float sa = 0.0f;
#pragma unroll 4
    for (int kk = 0; kk < n; kk++) sa += __ldg(&g_ang[(int)__ldg(&nlr[kk])]);
    float s1 = g_s1[row] + F1 * sa;           // includes dup contributions
    g_s1[row] = s1;
    g_enh1[row] = g_ang[row] + s1;
}

// ---------------- k_hop2: warp-per-row, sparse ffs dot (enh1 L2-resident) --------------
__global__ void __launch_bounds__(256) k_hop2() {
    int t = threadIdx.x, lane = t & 31, w = t >> 5;
    int row = blockIdx.x * 8 + w;
    const uint4* p4 = (const uint4*)(g_P2 + row * NW);
    uint4 m0 = p4[lane], m1 = p4[lane + 32];
    unsigned dw[8] = {m0.x, m0.y, m0.z, m0.w, m1.x, m1.y, m1.z, m1.w};
    float s = 0.0f;
#pragma unroll
    for (int q = 0; q < 8; q++) {
        unsigned x = dw[q];
        int base = (((q < 4 ? lane : lane + 32) * 4) + (q & 3)) * 32;
        while (x) {
            int b = __ffs((int)x) - 1;
            x &= (x - 1);
            s += __ldg(&g_enh1[base + b]);
        }
    }
#pragma unroll
    for (int o = 16; o; o >>= 1) s += __shfl_xor_sync(0xffffffffu, s, o);
    if (lane == 0) {
        float st2 = g_s1[row] + F2 * s;
        g_s2[row]   = st2;
        g_enh2[row] = g_enh1[row] + st2;
    }
}

// ---------------- k_dot: stream P3 rows + fp16 nibble LUT in smem (3 CTA/SM) -----------
#define DOT_SMEM (2048 * 16 * 2)     // 64 KB fp16 LUT
__global__ void __launch_bounds__(512, 3) k_dot(float* __restrict__ out) {
    extern __shared__ __half hlut[];
    int t = threadIdx.x, lane = t & 31, w = t >> 5;   // 16 warps

    for (int g = t; g < 2048; g += 512) {
        float f0 = __ldg(&g_enh2[g * 4]),     f1 = __ldg(&g_enh2[g * 4 + 1]);
        float f2 = __ldg(&g_enh2[g * 4 + 2]), f3 = __ldg(&g_enh2[g * 4 + 3]);
        __half* L = hlut + g * 16;
        int sw = g & 15;
#pragma unroll
        for (int n = 0; n < 16; n++) {
            float s = 0.0f;
            if (n & 1) s += f0;
            if (n & 2) s += f1;
            if (n & 4) s += f2;
            if (n & 8) s += f3;
            L[n ^ sw] = __float2half_rn(s);
        }
    }
    __syncthreads();

#pragma unroll
    for (int rr = 0; rr < 2; rr++) {               // 32 rows/block, grid 256
        int row = blockIdx.x * 32 + rr * 16 + w;
        const uint4* p4 = (const uint4*)(g_P3 + row * NW);   // coalesced stream
        uint4 m0 = p4[lane], m1 = p4[lane + 32];
        unsigned dw[8] = {m0.x, m0.y, m0.z, m0.w, m1.x, m1.y, m1.z, m1.w};
        float s = 0.0f;
#pragma unroll
        for (int q = 0; q < 8; q++) {
            unsigned x = dw[q];
            int wi = (q < 4 ? lane : lane + 32) * 4 + (q & 3);
#pragma unroll
            for (int hh = 0; hh < 8; hh++) {
                int hb = (hh + lane) & 7;              // lane-rotated order
                int g = wi * 8 + hb;
                unsigned nib = (x >> (4 * hb)) & 15u;
                s += __half2float(hlut[g * 16 + (nib ^ (unsigned)(g & 15))]);
            }
        }
#pragma unroll
        for (int o = 16; o; o >>= 1) s += __shfl_xor_sync(0xffffffffu, s, o);
        if (lane == 0) out[row] = __ldg(&g_enh2[row]) + __ldg(&g_s2[row]) + F3 * s;
    }
}

// ---------------- launch: MLP + P3-gather overlapped on a side stream ----------------
extern "C" void kernel_launch(void* const* d_in, const int* in_sizes, int n_in,
                              void* d_out, int out_size) {
    const float* coeffs = (const float*)d_in[0];
    const float* W0 = (const float*)d_in[1];
    const float* W1 = (const float*)d_in[2];
    const float* W2 = (const float*)d_in[3];
    const float* W3 = (const float*)d_in[4];
    const int*   ei = (const int*)d_in[5];
    int E = in_sizes[5] / 2;
    float* out = (float*)d_out;

    static cudaStream_t s2 = nullptr;
    static cudaEvent_t evFork = nullptr, evJoin = nullptr, evFork2 = nullptr, evJoin2 = nullptr;
    if (!s2) {
        cudaStreamCreateWithFlags(&s2, cudaStreamNonBlocking);
        cudaEventCreateWithFlags(&evFork, cudaEventDisableTiming);
        cudaEventCreateWithFlags(&evJoin, cudaEventDisableTiming);
        cudaEventCreateWithFlags(&evFork2, cudaEventDisableTiming);
        cudaEventCreateWithFlags(&evJoin2, cudaEventDisableTiming);
        cudaFuncSetAttribute(mlp_kernel, cudaFuncAttributeMaxDynamicSharedMemorySize, SM_MLP);
        cudaFuncSetAttribute(k_dot, cudaFuncAttributeMaxDynamicSharedMemorySize, DOT_SMEM);
    }

    prep_kernel<<<2048, 256>>>(W0, W1, W2);

    // fork 1: MLP on side stream, overlapped with adjacency build + P2 gather
    cudaEventRecord(evFork, 0);
    cudaStreamWaitEvent(s2, evFork, 0);
    mlp_kernel<<<NN / ROWS_CTA, 512, SM_MLP, s2>>>(coeffs, W3);
    cudaEventRecord(evJoin, s2);

    build_adj<<<(E + 255) / 256, 256>>>(ei, E);
    k_p2<<<NN / 8, 256>>>();

    // fork 2: P3 gather on side stream (depends only on k_p2), overlapped with hop chain
    cudaEventRecord(evFork2, 0);
    cudaStreamWaitEvent(s2, evFork2, 0);
    k_p3g<<<NN / 8, 256, 0, s2>>>();
    cudaEventRecord(evJoin2, s2);

    // main: angle-dependent chain (needs MLP)
    cudaStreamWaitEvent(0, evJoin, 0);
    k_dup<<<16, 256>>>();
    k_s1<<<NN / 32, 32>>>();
    k_hop2<<<NN / 8, 256>>>();

    // join: final dense dot
    cudaStreamWaitEvent(0, evJoin2, 0);
    k_dot<<<NN / 32, 512, DOT_SMEM>>>(out);
}